// round 10
// baseline (speedup 1.0000x reference)
#include <cuda_runtime.h>
#include <cuda_fp16.h>
#include <cstdint>
#include <math.h>

#define MAXN   4096
#define MAXD   512
#define NB     1024
#define MARGIN 0.3f
#define BIGD2  3.0e38f

// ---------------- scratch ----------------
__device__ __align__(16) __half g_Ehi[MAXN * MAXD];
__device__ float    g_sq[MAXN];
__device__ float    g_hp2[MAXN];
__device__ float    g_hpB2[MAXN];
__device__ unsigned g_hnfb[MAXN];
__device__ unsigned g_hnsemi[MAXN];
__device__ int      g_semiflag;
__device__ int      g_done;
__device__ int      g_ccount[NB];
__device__ int      g_coff[NB];
__device__ int      g_clist[MAXN];

__device__ __forceinline__ uint32_t smem_u32(const void* p) {
    uint32_t a;
    asm("{ .reg .u64 t; cvta.to.shared.u64 t, %1; cvt.u32.u64 %0, t; }" : "=r"(a) : "l"(p));
    return a;
}

#define CP_ASYNC16(dst, src) \
    asm volatile("cp.async.cg.shared.global [%0], [%1], 16;" :: "r"(dst), "l"(src))
#define CP_COMMIT() asm volatile("cp.async.commit_group;")
#define CP_WAIT2()  asm volatile("cp.async.wait_group 2;")

#define LDM4(r0, r1, r2, r3, addr)                                              \
    asm volatile("ldmatrix.sync.aligned.m8n8.x4.shared.b16 {%0,%1,%2,%3}, [%4];" \
        : "=r"(r0), "=r"(r1), "=r"(r2), "=r"(r3) : "r"(addr))

#define MMA16816(c, a, b0, b1)                                                   \
    asm volatile("mma.sync.aligned.m16n8k16.row.col.f32.f16.f16.f32 "            \
        "{%0,%1,%2,%3},{%4,%5,%6,%7},{%8,%9},{%0,%1,%2,%3};"                     \
        : "+f"((c)[0]), "+f"((c)[1]), "+f"((c)[2]), "+f"((c)[3])                 \
        : "r"((a)[0]), "r"((a)[1]), "r"((a)[2]), "r"((a)[3]), "r"(b0), "r"(b1))

// ---------------- kernel 0: convert(hi only) + row sq + per-row init ----------------
__global__ void convsq_kernel(const float* __restrict__ E, int d) {
    int row = blockIdx.x;
    int t = threadIdx.x;
    const float4* p = (const float4*)(E + (size_t)row * d);
    int d4 = d >> 2;
    float s = 0.f;
    for (int c = t; c < d4; c += blockDim.x) {
        float4 v = p[c];
        s += v.x * v.x + v.y * v.y + v.z * v.z + v.w * v.w;
        __half2 h01 = __halves2half2(__float2half(v.x), __float2half(v.y));
        __half2 h23 = __halves2half2(__float2half(v.z), __float2half(v.w));
        size_t o = (size_t)row * d + 4 * c;
        *(__half2*)(g_Ehi + o) = h01;
        *(__half2*)(g_Ehi + o + 2) = h23;
    }
    for (int o = 16; o; o >>= 1) s += __shfl_xor_sync(0xffffffffu, s, o);
    __shared__ float ws[4];
    int lane = t & 31, w = t >> 5;
    if (lane == 0) ws[w] = s;
    __syncthreads();
    if (t == 0) {
        float tot = 0.f;
        for (int k = 0; k < (int)(blockDim.x >> 5); k++) tot += ws[k];
        g_sq[row] = tot;
        g_hnfb[row] = 0u;
        g_hnsemi[row] = __float_as_uint(BIGD2);
        if (row == 0) { g_semiflag = 0; g_done = 0; }
    }
}

// ---------------- kernel 1: hist + scan + fill (single block) ----------------
__global__ void classlist_kernel(const int* __restrict__ labels, int n) {
    __shared__ int cnt[NB];
    __shared__ int s[NB];
    __shared__ int cur[NB];
    int t = threadIdx.x;
    cnt[t] = 0;
    __syncthreads();
    for (int i = t; i < n; i += blockDim.x) atomicAdd(&cnt[labels[i] & (NB - 1)], 1);
    __syncthreads();
    int v = cnt[t];
    s[t] = v;
    for (int off = 1; off < NB; off <<= 1) {
        __syncthreads();
        int u = (t >= off) ? s[t - off] : 0;
        __syncthreads();
        s[t] += u;
    }
    __syncthreads();
    int excl = s[t] - v;
    g_coff[t] = excl;
    g_ccount[t] = v;
    cur[t] = excl;
    __syncthreads();
    for (int i = t; i < n; i += blockDim.x) {
        int c = labels[i] & (NB - 1);
        int pos = atomicAdd(&cur[c], 1);
        g_clist[pos] = i;
    }
}

// ---------------- kernel 2: exact fp32 hardest positive (block per anchor) ----------
__global__ void hp_kernel(const float* __restrict__ E, const int* __restrict__ labels,
                          int n, int d) {
    int anchor = blockIdx.x;
    int lid = threadIdx.x & 31, wid = threadIdx.x >> 5;
    int c = labels[anchor] & (NB - 1);
    const float4* ea = (const float4*)(E + (size_t)anchor * d);
    int dk4 = d >> 7;
    float4 a0[MAXD / 128];
#pragma unroll
    for (int j = 0; j < MAXD / 128; j++) if (j < dk4) a0[j] = ea[lid + 32 * j];
    int beg = g_coff[c], cnt = g_ccount[c];
    float sqa = g_sq[anchor];
    float maxd2 = 0.f;
    for (int t = wid; t < cnt; t += 4) {
        int m = g_clist[beg + t];
        const float4* em = (const float4*)(E + (size_t)m * d);
        float dot = 0.f;
#pragma unroll
        for (int j = 0; j < MAXD / 128; j++)
            if (j < dk4) {
                float4 b = em[lid + 32 * j];
                dot += a0[j].x * b.x + a0[j].y * b.y + a0[j].z * b.z + a0[j].w * b.w;
            }
        for (int o = 16; o; o >>= 1) dot += __shfl_xor_sync(0xffffffffu, dot, o);
        float d2 = sqa + g_sq[m] - 2.f * dot;
        maxd2 = fmaxf(maxd2, d2);
    }
    __shared__ float wmax[4];
    if (lid == 0) wmax[wid] = maxd2;
    __syncthreads();
    if (threadIdx.x == 0) {
        float h2 = fmaxf(fmaxf(fmaxf(wmax[0], wmax[1]), fmaxf(wmax[2], wmax[3])), 1e-12f);
        g_hp2[anchor] = h2;
        float hp = sqrtf(h2);
        g_hpB2[anchor] = (hp + MARGIN) * (hp + MARGIN);
    }
}

// ------- kernel 3: persistent HMMA GEMM, rolling 4-stage pipeline, fused finalize -----
#define BK      64
#define TILEB   16384
#define STAGEB  (2 * TILEB)
#define NSTAGE  4
#define AUXO    (NSTAGE * STAGEB)
#define SMEM_DYN (AUXO + 6144)

__device__ __forceinline__ uint32_t swz(int r, int ch) {
    return (uint32_t)(r * 128 + ((ch ^ (r & 7)) << 4));
}

__device__ __forceinline__ void tilemap(int t, int& rowBase, int& colBase) {
    int by = (int)((sqrtf(8.f * (float)t + 1.f) - 1.f) * 0.5f);
    while ((by + 1) * (by + 2) / 2 <= t) by++;
    while (by * (by + 1) / 2 > t) by--;
    int bx = t - by * (by + 1) / 2;
    rowBase = by * 128;
    colBase = bx * 128;
}

__global__ __launch_bounds__(512, 1) void gemm_kernel(const int* __restrict__ labels,
                                                      int n, int d, int ntiles,
                                                      float* __restrict__ out) {
    extern __shared__ char sm[];
    uint32_t sb = smem_u32(sm);
    int tid = threadIdx.x, lane = tid & 31, wid = tid >> 5;
    int wm = wid >> 2, wn = wid & 3;

    float*    s_sqc  = (float*)(sm + AUXO);
    int*      s_labc = (int*)(sm + AUXO + 512);
    float*    s_sqr  = (float*)(sm + AUXO + 1024);
    int*      s_labr = (int*)(sm + AUXO + 1536);
    float*    s_hp2r = (float*)(sm + AUXO + 2048);
    float*    s_hpBr = (float*)(sm + AUXO + 2560);
    float*    s_hp2c = (float*)(sm + AUXO + 3072);
    float*    s_hpBc = (float*)(sm + AUXO + 3584);
    unsigned* shRmax = (unsigned*)(sm + AUXO + 4096);
    unsigned* shRmin = (unsigned*)(sm + AUXO + 4608);
    unsigned* shCmax = (unsigned*)(sm + AUXO + 5120);
    unsigned* shCmin = (unsigned*)(sm + AUXO + 5632);

    // per-thread cp.async slots (tile-relative)
    int  eoff[4];
    uint32_t soff[4];
#pragma unroll
    for (int j = 0; j < 4; j++) {
        int tt = j >> 1;
        int w = ((j & 1) << 9) + tid;
        int r = w >> 3, ch = w & 7;
        eoff[j] = r * d + ch * 8;
        soff[j] = (uint32_t)(tt * TILEB) + swz(r, ch);
    }

    // per-lane ldmatrix addresses for 4 k16-steps
    int r0A = wm * 32 + (lane & 15);
    int cA  = lane >> 4;
    int r0B = wn * 32 + (lane & 7) + ((lane >> 4) & 1) * 8;
    int cB  = (lane >> 3) & 1;
    uint32_t aoff[4], boff[4];
#pragma unroll
    for (int s = 0; s < 4; s++) {
        aoff[s] = swz(r0A, 2 * s + cA);
        boff[s] = swz(r0B, 2 * s + cB);
    }

    float acc[2][4][4];
#pragma unroll
    for (int im = 0; im < 2; im++)
#pragma unroll
        for (int in = 0; in < 4; in++)
#pragma unroll
            for (int e = 0; e < 4; e++) acc[im][in][e] = 0.f;

    auto issue = [&](int st, int rB, int cB_, int cc) {
#pragma unroll
        for (int j = 0; j < 4; j++) {
            int base = (j < 2) ? rB : cB_;
            const __half* src = g_Ehi + (size_t)base * d + eoff[j] + cc * BK;
            CP_ASYNC16(sb + (uint32_t)st * STAGEB + soff[j], src);
        }
    };
    auto load_aux = [&](int rB, int cB_) {
        if (tid < 128) {
            s_sqc[tid]  = g_sq[cB_ + tid];  s_labc[tid] = labels[cB_ + tid];
            s_sqr[tid]  = g_sq[rB + tid];   s_labr[tid] = labels[rB + tid];
            s_hp2r[tid] = g_hp2[rB + tid];  s_hpBr[tid] = g_hpB2[rB + tid];
            s_hp2c[tid] = g_hp2[cB_ + tid]; s_hpBc[tid] = g_hpB2[cB_ + tid];
            shRmax[tid] = 0u; shRmin[tid] = __float_as_uint(BIGD2);
            shCmax[tid] = 0u; shCmin[tid] = __float_as_uint(BIGD2);
        }
    };
    auto compute = [&](uint32_t base) {
#pragma unroll
        for (int h = 0; h < 2; h++) {
            uint32_t ah[2][2][4], bh[2][4][2];
#pragma unroll
            for (int s2 = 0; s2 < 2; s2++) {
                int s = 2 * h + s2;
#pragma unroll
                for (int im = 0; im < 2; im++) {
                    uint32_t aA = base + im * 2048 + aoff[s];
                    LDM4(ah[s2][im][0], ah[s2][im][1], ah[s2][im][2], ah[s2][im][3], aA);
                }
#pragma unroll
                for (int p = 0; p < 2; p++) {
                    uint32_t aB = base + TILEB + p * 2048 + boff[s];
                    LDM4(bh[s2][2 * p][0], bh[s2][2 * p][1],
                         bh[s2][2 * p + 1][0], bh[s2][2 * p + 1][1], aB);
                }
            }
#pragma unroll
            for (int s2 = 0; s2 < 2; s2++)
#pragma unroll
                for (int im = 0; im < 2; im++)
#pragma unroll
                    for (int in = 0; in < 4; in++)
                        MMA16816(acc[im][in], ah[s2][im], bh[s2][in][0], bh[s2][in][1]);
        }
    };

    int t = blockIdx.x;
    int curR, curC;
    tilemap(t, curR, curC);
    bool hasNext = (t + gridDim.x) < ntiles;
    int nxtR = 0, nxtC = 0;
    if (hasNext) tilemap(t + gridDim.x, nxtR, nxtC);

    load_aux(curR, curC);
    issue(0, curR, curC, 0); CP_COMMIT();
    issue(1, curR, curC, 1); CP_COMMIT();
    issue(2, curR, curC, 2); CP_COMMIT();
    int sW = 3, sR = 0;

    while (true) {
        for (int c = 0; c < 8; c++) {
            CP_WAIT2();
            __syncthreads();
            int pc = c + 3;
            if (pc < 8) issue(sW, curR, curC, pc);
            else if (hasNext) issue(sW, nxtR, nxtC, pc - 8);
            CP_COMMIT();
            sW = (sW + 1) & 3;
            compute(sb + (uint32_t)sR * STAGEB);
            sR = (sR + 1) & 3;
        }

        bool diag = (curR == curC);
        // ---- epilogue: row-side ----
#pragma unroll
        for (int im = 0; im < 2; im++)
#pragma unroll
            for (int eh = 0; eh < 2; eh++) {
                int rloc = wm * 32 + im * 16 + (lane >> 2) + eh * 8;
                float sqr = s_sqr[rloc];
                int   labr = s_labr[rloc];
                float A = s_hp2r[rloc], B = s_hpBr[rloc];
                float mx = 0.f, mn = BIGD2;
#pragma unroll
                for (int in = 0; in < 4; in++)
#pragma unroll
                    for (int ec = 0; ec < 2; ec++) {
                        int cloc = wn * 32 + in * 8 + (lane & 3) * 2 + ec;
                        float dot = acc[im][in][eh * 2 + ec];
                        float d2 = fmaxf(sqr + s_sqc[cloc] - 2.f * dot, 1e-12f);
                        if (labr != s_labc[cloc]) {
                            mx = fmaxf(mx, d2);
                            if (d2 > A && d2 < B) mn = fminf(mn, d2);
                        }
                    }
                if (mx > 0.f) atomicMax(&shRmax[rloc], __float_as_uint(mx));
                if (mn < BIGD2) atomicMin(&shRmin[rloc], __float_as_uint(mn));
            }
        // ---- epilogue: col-side ----
        if (!diag) {
#pragma unroll
            for (int in = 0; in < 4; in++)
#pragma unroll
                for (int ec = 0; ec < 2; ec++) {
                    int cloc = wn * 32 + in * 8 + (lane & 3) * 2 + ec;
                    float sqc = s_sqc[cloc];
                    int   labc = s_labc[cloc];
                    float A = s_hp2c[cloc], B = s_hpBc[cloc];
                    float mx = 0.f, mn = BIGD2;
#pragma unroll
                    for (int im = 0; im < 2; im++)
#pragma unroll
                        for (int eh = 0; eh < 2; eh++) {
                            int rloc = wm * 32 + im * 16 + (lane >> 2) + eh * 8;
                            float dot = acc[im][in][eh * 2 + ec];
                            float d2 = fmaxf(s_sqr[rloc] + sqc - 2.f * dot, 1e-12f);
                            if (labc != s_labr[rloc]) {
                                mx = fmaxf(mx, d2);
                                if (d2 > A && d2 < B) mn = fminf(mn, d2);
                            }
                        }
                    if (mx > 0.f) atomicMax(&shCmax[cloc], __float_as_uint(mx));
                    if (mn < BIGD2) atomicMin(&shCmin[cloc], __float_as_uint(mn));
                }
        }
        __syncthreads();
        if (tid < 128) {
            if (shRmax[tid]) atomicMax(&g_hnfb[curR + tid], shRmax[tid]);
            if (shRmin[tid] != __float_as_uint(BIGD2)) {
                atomicMin(&g_hnsemi[curR + tid], shRmin[tid]);
                g_semiflag = 1;
            }
            if (!diag) {
                if (shCmax[tid]) atomicMax(&g_hnfb[curC + tid], shCmax[tid]);
                if (shCmin[tid] != __float_as_uint(BIGD2)) {
                    atomicMin(&g_hnsemi[curC + tid], shCmin[tid]);
                    g_semiflag = 1;
                }
            }
        }

        t += gridDim.x;
        if (t >= ntiles) break;
        curR = nxtR; curC = nxtC;
        hasNext = (t + gridDim.x) < ntiles;
        if (hasNext) tilemap(t + gridDim.x, nxtR, nxtC);
        load_aux(curR, curC);
#pragma unroll
        for (int im = 0; im < 2; im++)
#pragma unroll
            for (int in = 0; in < 4; in++)
#pragma unroll
                for (int e = 0; e < 4; e++) acc[im][in][e] = 0.f;
    }

    // ---- fused finalize: last CTA computes the loss ----
    __shared__ int sdone;
    __shared__ float fsum[16];
    __shared__ int   fcnt[16];
    __threadfence();
    if (tid == 0) sdone = (atomicAdd(&g_done, 1) == (int)gridDim.x - 1) ? 1 : 0;
    __syncthreads();
    if (sdone) {
        bool useSemi = (g_semiflag != 0);
        float sum = 0.f;
        int cnt = 0;
        for (int i = tid; i < n; i += blockDim.x) {
            float hp = sqrtf(g_hp2[i]);
            unsigned hb = useSemi ? g_hnsemi[i] : g_hnfb[i];
            float hn = sqrtf(__uint_as_float(hb));
            float tr = hp - hn + MARGIN;
            if (tr < 0.f) tr = 0.f;
            sum += tr;
            if (tr > 0.f) cnt++;
        }
        for (int o = 16; o; o >>= 1) {
            sum += __shfl_xor_sync(0xffffffffu, sum, o);
            cnt += __shfl_xor_sync(0xffffffffu, cnt, o);
        }
        if (lane == 0) { fsum[wid] = sum; fcnt[wid] = cnt; }
        __syncthreads();
        if (tid == 0) {
            float s = 0.f; int c = 0;
            for (int k = 0; k < 16; k++) { s += fsum[k]; c += fcnt[k]; }
            out[0] = (c > 0) ? (s / (float)c) : 0.0f;
        }
    }
}

// ---------------- launch ----------------
extern "C" void kernel_launch(void* const* d_in, const int* in_sizes, int n_in,
                              void* d_out, int out_size) {
    const float* E = (const float*)d_in[0];
    const int* labels = (const int*)d_in[1];
    int n = in_sizes[1];
    int d = in_sizes[0] / n;

    cudaFuncSetAttribute(gemm_kernel, cudaFuncAttributeMaxDynamicSharedMemorySize, SMEM_DYN);

    convsq_kernel<<<n, 128>>>(E, d);
    classlist_kernel<<<1, NB>>>(labels, n);
    hp_kernel<<<n, 128>>>(E, labels, n, d);
    int nb = n / 128;
    int ntiles = nb * (nb + 1) / 2;
    int G = 132;
    if (ntiles < G) G = ntiles;
    gemm_kernel<<<G, 512, SMEM_DYN>>>(labels, n, d, ntiles, (float*)d_out);
}